// round 7
// baseline (speedup 1.0000x reference)
#include <cuda_runtime.h>
#include <cuda_fp16.h>
#include <cstdint>

// HistoGAN histogram loss via mma.sync f16 + ldmatrix, K-contiguous swizzled
// operands, KC=64, double-buffered stages, one sync per chunk, f32 MUFU rcp.
// 3 CTAs/SM (PARTS=55, launch_bounds(192,3)) to cover sync/latency bubbles.
//
// A-stack (128 rows, K=px): rows 0-63 = Iy*k01, rows 64-127 = Iy*k02
// B0 = k02 (64 cols), B1 = k12 (64 cols).
//   G_AB = Atop x B0, G_AC = Atop x B1, G_BC = Abot x B1
// hist0[u,v]=G_AB[u,v]; hist1[u,v]=G_AC[63-u,v]; hist2[u,v]=G_BC[63-u,63-v]
//
// SMEM operand layout: row-major, 64 f16 per row (=128B), 16B-block swizzle
// blk' = blk ^ (row & 7). Producer STS.128 conflict-free; consumer ldmatrix.x4.

#define EPSV  (6.4f / 255.0f)
#define NPIX  65536
#define PARTS 55
#define QSTEP 4.761904761904762f   /* 300/63 */
#define KC    64

#define A_OFF   0
#define B0_OFF  16384
#define B1_OFF  24576
#define STAGEB  32768
#define DSMEMB  (2 * STAGEB)

__device__ float g_G[8 * 3 * 4096];   // [B][3][64][64] raw
__device__ float g_sum[8];            // per-batch total mass
__device__ float g_acc;               // Hellinger sum accumulator
__device__ unsigned g_done;           // hell CTA completion counter

static __device__ __forceinline__ float rcpa(float x) {
    float r; asm("rcp.approx.f32 %0, %1;" : "=f"(r) : "f"(x)); return r;
}
static __device__ __forceinline__ uint32_t s2u(const void* p) {
    uint32_t a;
    asm("{ .reg .u64 t; cvta.to.shared.u64 t, %1; cvt.u32.u64 %0, t; }"
        : "=r"(a) : "l"(p));
    return a;
}
static __device__ __forceinline__ uint32_t packh2(float lo, float hi) {
    __half2 h = __floats2half2_rn(lo, hi);
    return *(uint32_t*)&h;
}
static __device__ __forceinline__ void sts128(uint32_t addr, uint32_t w0,
        uint32_t w1, uint32_t w2, uint32_t w3) {
    asm volatile("st.shared.v4.b32 [%0], {%1,%2,%3,%4};"
        :: "r"(addr), "r"(w0), "r"(w1), "r"(w2), "r"(w3));
}
static __device__ __forceinline__ void ldmx4(uint32_t& r0, uint32_t& r1,
        uint32_t& r2, uint32_t& r3, uint32_t addr) {
    asm volatile("ldmatrix.sync.aligned.m8n8.x4.shared.b16 {%0,%1,%2,%3}, [%4];"
        : "=r"(r0), "=r"(r1), "=r"(r2), "=r"(r3) : "r"(addr));
}
static __device__ __forceinline__ void mma16(float* c,
        uint32_t a0, uint32_t a1, uint32_t a2, uint32_t a3,
        uint32_t b0, uint32_t b1) {
    asm("mma.sync.aligned.m16n8k16.row.col.f32.f16.f16.f32 "
        "{%0,%1,%2,%3},{%4,%5,%6,%7},{%8,%9},{%0,%1,%2,%3};"
        : "+f"(c[0]), "+f"(c[1]), "+f"(c[2]), "+f"(c[3])
        : "r"(a0), "r"(a1), "r"(a2), "r"(a3), "r"(b0), "r"(b1));
}

static __device__ __forceinline__ float4 pix_math(float rr, float gg, float bb) {
    float r  = fminf(fmaxf(fmaf(rr, 0.5f, 0.5f), 0.f), 1.f);
    float g  = fminf(fmaxf(fmaf(gg, 0.5f, 0.5f), 0.f), 1.f);
    float bl = fminf(fmaxf(fmaf(bb, 0.5f, 0.5f), 0.f), 1.f);
    float iy = sqrtf(fmaf(r, r, fmaf(g, g, fmaf(bl, bl, EPSV))));
    float lr = __logf(r + EPSV), lg = __logf(g + EPSV), lb = __logf(bl + EPSV);
    return make_float4(lr - lg, lr - lb, lg - lb, iy);
}

__global__ void __launch_bounds__(192, 3)
hist_kernel(const float* __restrict__ rgbd) {
    extern __shared__ char dsm[];                 // 2 operand stages
    __shared__ float sd[2][3][64];                // d01/d02/d12 per pixel, x2
    __shared__ float siy[2][64];                  // Iy per pixel, x2

    const uint32_t smb = s2u(dsm);
    const int tid  = threadIdx.x;
    const int lane = tid & 31;
    const int w    = tid >> 5;
    const int b    = blockIdx.x / PARTS;
    const int part = blockIdx.x % PARTS;
    const int start = (int)((long long)part       * NPIX / PARTS);
    const int end   = (int)((long long)(part + 1) * NPIX / PARTS);
    const float* R  = rgbd + (size_t)b * 4 * NPIX;

    // ---- producer mapping: vec = tid>>6 (0:A-top, 1:B0+A-bot, 2:B1) ----
    const int   vec  = tid >> 6;
    const int   bin  = tid & 63;
    const float negd = 150.0f - (float)bin * QSTEP;
    const int   swp  = bin & 7;
    uint32_t dst1, dst2 = 0;
    if (vec == 0)      { dst1 = A_OFF  + bin * 128; }
    else if (vec == 1) { dst1 = B0_OFF + bin * 128; dst2 = A_OFF + (64 + bin) * 128; }
    else               { dst1 = B1_OFF + bin * 128; }

    // ---- consumer mapping: warp -> matrix m, row-half rh ----
    const int m  = w >> 1;                 // 0=AB, 1=AC, 2=BC
    const int rh = w & 1;
    const int Rb = ((m == 2) ? 64 : 0) + 32 * rh;
    const uint32_t Boff = (m == 0) ? B0_OFF : B1_OFF;
    // A ldmatrix lane geometry (rows fixed per lane)
    const int rowA  = Rb + (lane & 7) + 8 * ((lane >> 3) & 1);
    const int swA   = rowA & 7;
    const int koffA = lane >> 4;                 // 0 or 1 (k-block +8)
    const uint32_t byteA0 = (uint32_t)(A_OFF + rowA * 128);
    const uint32_t byteA1 = byteA0 + 16 * 128;   // rows +16
    // B ldmatrix lane geometry
    const int colB  = (lane & 7) + ((lane >> 1) & 8);   // +8 for lanes 16-31
    const int swB   = lane & 7;
    const int koffB = (lane >> 3) & 1;
    const uint32_t byteBbase = Boff + (uint32_t)colB * 128;

    float acc[2][8][4];
#pragma unroll
    for (int s = 0; s < 2; ++s)
#pragma unroll
        for (int t = 0; t < 8; ++t)
#pragma unroll
            for (int i = 0; i < 4; ++i) acc[s][t][i] = 0.f;

    const int nch = (end - start + KC - 1) / KC;

    // pixel prep for chunk 0 (warps 4,5)
    if (tid >= 128) {
        const int q = tid - 128;
        const int px = start + q;
        float4 P = make_float4(0.f, 0.f, 0.f, 0.f);
        if (px < end) P = pix_math(R[px], R[NPIX + px], R[2 * NPIX + px]);
        sd[0][0][q] = P.x; sd[0][1][q] = P.y; sd[0][2][q] = P.z; siy[0][q] = P.w;
    }
    __syncthreads();

    for (int c = 0; c < nch; ++c) {
        const int buf = c & 1;
        const uint32_t stg = smb + buf * STAGEB;

        // early LDG for next chunk's pixels
        float rr = 0.f, gg = 0.f, bb = 0.f;
        int pvalid = 0;
        if (tid >= 128 && c + 1 < nch) {
            const int px = start + (c + 1) * KC + (tid - 128);
            if (px < end) {
                pvalid = 1;
                rr = R[px]; gg = R[NPIX + px]; bb = R[2 * NPIX + px];
            }
        }

        // ---- produce: 8 blocks of 8 pixels, STS.128 each ----
#pragma unroll
        for (int j = 0; j < 8; ++j) {
            const float4 dA = *(const float4*)&sd[buf][vec][8 * j];
            const float4 dB = *(const float4*)&sd[buf][vec][8 * j + 4];
            float k0 = rcpa(fmaf(fmaf(dA.x, 50.f, negd), fmaf(dA.x, 50.f, negd), 1.f));
            float k1 = rcpa(fmaf(fmaf(dA.y, 50.f, negd), fmaf(dA.y, 50.f, negd), 1.f));
            float k2 = rcpa(fmaf(fmaf(dA.z, 50.f, negd), fmaf(dA.z, 50.f, negd), 1.f));
            float k3 = rcpa(fmaf(fmaf(dA.w, 50.f, negd), fmaf(dA.w, 50.f, negd), 1.f));
            float k4 = rcpa(fmaf(fmaf(dB.x, 50.f, negd), fmaf(dB.x, 50.f, negd), 1.f));
            float k5 = rcpa(fmaf(fmaf(dB.y, 50.f, negd), fmaf(dB.y, 50.f, negd), 1.f));
            float k6 = rcpa(fmaf(fmaf(dB.z, 50.f, negd), fmaf(dB.z, 50.f, negd), 1.f));
            float k7 = rcpa(fmaf(fmaf(dB.w, 50.f, negd), fmaf(dB.w, 50.f, negd), 1.f));
            const uint32_t off = (uint32_t)(((j ^ swp) << 4));
            if (vec == 2) {
                sts128(stg + dst1 + off,
                       packh2(k0, k1), packh2(k2, k3),
                       packh2(k4, k5), packh2(k6, k7));
            } else {
                const float4 iA = *(const float4*)&siy[buf][8 * j];
                const float4 iB = *(const float4*)&siy[buf][8 * j + 4];
                if (vec == 1)   // raw k02 -> B0
                    sts128(stg + dst1 + off,
                           packh2(k0, k1), packh2(k2, k3),
                           packh2(k4, k5), packh2(k6, k7));
                const uint32_t dA2 = (vec == 0) ? (stg + dst1 + off) : (stg + dst2 + off);
                sts128(dA2,
                       packh2(k0 * iA.x, k1 * iA.y), packh2(k2 * iA.z, k3 * iA.w),
                       packh2(k4 * iB.x, k5 * iB.y), packh2(k6 * iB.z, k7 * iB.w));
            }
        }

        // finish pixel prep for next chunk into the other buffers
        if (tid >= 128 && c + 1 < nch) {
            float4 P = make_float4(0.f, 0.f, 0.f, 0.f);
            if (pvalid) P = pix_math(rr, gg, bb);
            const int q = tid - 128;
            sd[buf ^ 1][0][q] = P.x; sd[buf ^ 1][1][q] = P.y;
            sd[buf ^ 1][2][q] = P.z; siy[buf ^ 1][q] = P.w;
        }
        __syncthreads();

        // ---- MMA: 4 k16 steps via ldmatrix.x4, loads batched up front ----
#pragma unroll
        for (int ks = 0; ks < 4; ++ks) {
            uint32_t a0[4], a1[4], bm[4][4];
            const uint32_t kxA = (uint32_t)(((2 * ks + koffA) ^ swA) << 4);
            const uint32_t kxB = (uint32_t)(((2 * ks + koffB) ^ swB) << 4);
            ldmx4(a0[0], a0[1], a0[2], a0[3], stg + byteA0 + kxA);
            ldmx4(a1[0], a1[1], a1[2], a1[3], stg + byteA1 + kxA);
#pragma unroll
            for (int j = 0; j < 4; ++j)
                ldmx4(bm[j][0], bm[j][1], bm[j][2], bm[j][3],
                      stg + byteBbase + (uint32_t)(16 * j * 128) + kxB);
#pragma unroll
            for (int j = 0; j < 4; ++j) {
                mma16(acc[0][2 * j],     a0[0], a0[1], a0[2], a0[3], bm[j][0], bm[j][1]);
                mma16(acc[0][2 * j + 1], a0[0], a0[1], a0[2], a0[3], bm[j][2], bm[j][3]);
                mma16(acc[1][2 * j],     a1[0], a1[1], a1[2], a1[3], bm[j][0], bm[j][1]);
                mma16(acc[1][2 * j + 1], a1[0], a1[1], a1[2], a1[3], bm[j][2], bm[j][3]);
            }
        }
    }

    // ---- per-batch mass for normalization ----
    float lsum = 0.f;
#pragma unroll
    for (int s = 0; s < 2; ++s)
#pragma unroll
        for (int t = 0; t < 8; ++t)
#pragma unroll
            for (int i = 0; i < 4; ++i) lsum += acc[s][t][i];
#pragma unroll
    for (int o = 16; o > 0; o >>= 1) lsum += __shfl_xor_sync(~0u, lsum, o);
    if (lane == 0) atomicAdd(&g_sum[b], lsum);

    // ---- flush partial G ----
    float* Gm = g_G + (size_t)b * 3 * 4096 + m * 4096;
    const int urow = 32 * rh + (lane >> 2);
    const int col  = 2 * (lane & 3);
#pragma unroll
    for (int s = 0; s < 2; ++s) {
#pragma unroll
        for (int t = 0; t < 8; ++t) {
            float* p0 = Gm + (urow + 16 * s) * 64 + 8 * t + col;
            atomicAdd(p0,              acc[s][t][0]);
            atomicAdd(p0 + 1,          acc[s][t][1]);
            atomicAdd(p0 + 8 * 64,     acc[s][t][2]);
            atomicAdd(p0 + 8 * 64 + 1, acc[s][t][3]);
        }
    }
}

// ---- Hellinger: 96 CTAs (batch x matrix x quarter); re-zeroes g_G ----
__global__ void hell_kernel(const float* __restrict__ th,
                            float* __restrict__ out, int B) {
    __shared__ float sh[8];
    const int bc  = blockIdx.x >> 2;      // batch*3 + matrix
    const int sub = blockIdx.x & 3;       // quarter
    const int b   = bc / 3, c = bc % 3;
    const float inv = 1.0f / (g_sum[b] + EPSV);
    float* Gb = g_G + (size_t)b * 3 * 4096 + c * 4096;

    float a = 0.f;
#pragma unroll
    for (int it = 0; it < 4; ++it) {
        const int i = sub * 1024 + it * 256 + threadIdx.x;
        const int u = i >> 6, v = i & 63;
        int addr;
        if (c == 0)      addr = i;
        else if (c == 1) addr = ((63 - u) << 6) + v;
        else             addr = ((63 - u) << 6) + (63 - v);
        const float h = Gb[addr] * inv;
        Gb[addr] = 0.f;                       // reset for next graph replay
        const float d = sqrtf(th[c * 4096 + i]) - sqrtf(h);
        a = fmaf(d, d, a);
    }
#pragma unroll
    for (int o = 16; o > 0; o >>= 1) a += __shfl_xor_sync(~0u, a, o);
    if ((threadIdx.x & 31) == 0) sh[threadIdx.x >> 5] = a;
    __syncthreads();
    if (threadIdx.x == 0) {
        float s = 0.f;
#pragma unroll
        for (int i = 0; i < 8; ++i) s += sh[i];
        atomicAdd(&g_acc, s);
        __threadfence();
        const unsigned rank = atomicAdd(&g_done, 1u);
        if (rank == (unsigned)(12 * B - 1)) {      // last CTA finalizes
            __threadfence();
            out[0] = sqrtf(g_acc) * (0.70710678118654752f / (float)B);
            g_acc = 0.f;
            g_done = 0u;
#pragma unroll
            for (int i = 0; i < 8; ++i) g_sum[i] = 0.f;
        }
    }
}

extern "C" void kernel_launch(void* const* d_in, const int* in_sizes, int n_in,
                              void* d_out, int out_size) {
    const float* rgbd = (const float*)d_in[0];
    const float* th   = (const float*)d_in[1];
    float* out        = (float*)d_out;

    const int B = in_sizes[0] / (4 * NPIX);   // 8

    cudaFuncSetAttribute(hist_kernel,
                         cudaFuncAttributeMaxDynamicSharedMemorySize, DSMEMB);
    hist_kernel<<<B * PARTS, 192, DSMEMB>>>(rgbd);
    hell_kernel<<<B * 12, 256>>>(th, out, B);
}